// round 8
// baseline (speedup 1.0000x reference)
#include <cuda_runtime.h>
#include <cuda_fp16.h>
#include <cstdint>

// Problem constants (fixed by the dataset)
#define MAXN      100000
#define MAXE      2000000
#define F_IN      256
#define HC        128       // H*C = 2*64
#define NEG_SLOPE 0.2f

// Projected features in fp16: xl (source path) and xr (target path), [N][128]
__device__ __half g_xl_h[(size_t)MAXN * HC];
__device__ __half g_xr_h[(size_t)MAXN * HC];

// CSR-by-destination scratch
__device__ int g_cnt[MAXN + 4];      // in-degree histogram (padded for int4)
__device__ int g_row[MAXN + 1];      // row offsets
__device__ int g_cur[MAXN];          // scatter cursors
__device__ int g_srcs[MAXE];         // src node per edge, grouped by dst
__device__ int g_blksum[256];        // per-block sums for the scan
__device__ int g_blkoff[256];        // exclusive block offsets

// ---------------------------------------------------------------------------
// CSR build: zero-hist -> histogram -> 3-pass hierarchical scan -> scatter
// ---------------------------------------------------------------------------
__global__ void hist_zero_kernel(int n4) {
    int i = blockIdx.x * blockDim.x + threadIdx.x;
    if (i < n4) reinterpret_cast<int4*>(g_cnt)[i] = make_int4(0, 0, 0, 0);
}

__global__ void hist_kernel(const int* __restrict__ ei, int E) {
    int i = blockIdx.x * blockDim.x + threadIdx.x;
    if (i < E) atomicAdd(&g_cnt[ei[E + i]], 1);
}

// Pass 1: per-block (1024 elements) reduction -> g_blksum
__global__ __launch_bounds__(256) void scan1_kernel(int n) {
    const int b = blockIdx.x, tid = threadIdx.x;
    const int i0 = b * 1024 + tid * 4;
    int s0 = 0;
    if (i0 + 3 < n) {
        int4 v = *reinterpret_cast<const int4*>(&g_cnt[i0]);
        s0 = v.x + v.y + v.z + v.w;
    } else {
        for (int j = 0; j < 4; j++) if (i0 + j < n) s0 += g_cnt[i0 + j];
    }
#pragma unroll
    for (int off = 16; off; off >>= 1)
        s0 += __shfl_xor_sync(0xffffffffu, s0, off);
    __shared__ int ws[8];
    if ((tid & 31) == 0) ws[tid >> 5] = s0;
    __syncthreads();
    if (tid == 0) {
        int t = 0;
#pragma unroll
        for (int j = 0; j < 8; j++) t += ws[j];
        g_blksum[b] = t;
    }
}

// Pass 2: scan the (<=256) block sums in one block; also set g_row[n] = E
__global__ __launch_bounds__(256) void scan2_kernel(int nb, int n, int E) {
    const int tid = threadIdx.x;
    int v = (tid < nb) ? g_blksum[tid] : 0;
    __shared__ int s[256];
    s[tid] = v;
    __syncthreads();
#pragma unroll
    for (int off = 1; off < 256; off <<= 1) {
        int t = (tid >= off) ? s[tid - off] : 0;
        __syncthreads();
        s[tid] += t;
        __syncthreads();
    }
    if (tid < nb) g_blkoff[tid] = s[tid] - v;   // exclusive
    if (tid == 0) g_row[n] = E;
}

// Pass 3: per-block exclusive scan + block offset -> g_row, g_cur
__global__ __launch_bounds__(256) void scan3_kernel(int n) {
    const int b = blockIdx.x, tid = threadIdx.x;
    const int lane = tid & 31, wid = tid >> 5;
    const int i0 = b * 1024 + tid * 4;
    int c0 = 0, c1 = 0, c2 = 0, c3 = 0;
    if (i0 + 3 < n) {
        int4 v = *reinterpret_cast<const int4*>(&g_cnt[i0]);
        c0 = v.x; c1 = v.y; c2 = v.z; c3 = v.w;
    } else {
        if (i0 + 0 < n) c0 = g_cnt[i0 + 0];
        if (i0 + 1 < n) c1 = g_cnt[i0 + 1];
        if (i0 + 2 < n) c2 = g_cnt[i0 + 2];
        if (i0 + 3 < n) c3 = g_cnt[i0 + 3];
    }
    const int tsum = c0 + c1 + c2 + c3;
    int incl = tsum;
#pragma unroll
    for (int off = 1; off < 32; off <<= 1) {
        int t = __shfl_up_sync(0xffffffffu, incl, off);
        if (lane >= off) incl += t;
    }
    const int excl = incl - tsum;
    __shared__ int ws[8];
    __shared__ int wso[8];
    if (lane == 31) ws[wid] = incl;
    __syncthreads();
    if (tid == 0) {
        int r = 0;
#pragma unroll
        for (int j = 0; j < 8; j++) { wso[j] = r; r += ws[j]; }
    }
    __syncthreads();
    int base = g_blkoff[b] + wso[wid] + excl;
    if (i0 + 0 < n) { g_row[i0 + 0] = base; g_cur[i0 + 0] = base; base += c0; }
    if (i0 + 1 < n) { g_row[i0 + 1] = base; g_cur[i0 + 1] = base; base += c1; }
    if (i0 + 2 < n) { g_row[i0 + 2] = base; g_cur[i0 + 2] = base; base += c2; }
    if (i0 + 3 < n) { g_row[i0 + 3] = base; g_cur[i0 + 3] = base; base += c3; }
}

__global__ void scatter_kernel(const int* __restrict__ ei, int E) {
    int i = blockIdx.x * blockDim.x + threadIdx.x;
    if (i >= E) return;
    int s = ei[i];
    int d = ei[E + i];
    int pos = atomicAdd(&g_cur[d], 1);
    g_srcs[pos] = s;
}

// ---------------------------------------------------------------------------
// K1: fp16 tensor-core projection GEMM (m16n8k16, fp32 accumulate).
//   blockIdx.y == 0 : xl = x @ Wl^T + bl -> g_xl_h
//   blockIdx.y == 1 : xr = x @ Wr^T + br -> g_xr_h
// 128x128 block tile, BK=32 double-buffered, 8 warps (4Mx2N),
// warp tile 32x64 = 2x8 mma tiles of m16n8k16.
// Smem k-permute per 16-k group: order [0,1,8,9, 2,3,10,11, 4,5,12,13,
// 6,7,14,15], so each thread's fragment pairs (k,k+1) and (k+8,k+9) are
// 4 consecutive halves -> single LDS.64 per fragment pair.
// Rows padded to 48 halves (96B = 24 banks -> conflict-free 16-lane phases).
// ---------------------------------------------------------------------------
__device__ __forceinline__ uint4 pack8h(float4 p, float4 q) {
    // halves order: p0 p1 q0 q1 p2 p3 q2 q3  (matches the k-permute)
    uint4 r;
    __half2 h;
    h = __float22half2_rn(make_float2(p.x, p.y)); r.x = *reinterpret_cast<unsigned*>(&h);
    h = __float22half2_rn(make_float2(q.x, q.y)); r.y = *reinterpret_cast<unsigned*>(&h);
    h = __float22half2_rn(make_float2(p.z, p.w)); r.z = *reinterpret_cast<unsigned*>(&h);
    h = __float22half2_rn(make_float2(q.z, q.w)); r.w = *reinterpret_cast<unsigned*>(&h);
    return r;
}

__global__ __launch_bounds__(256) void gemm_fp16_kernel(
    const float* __restrict__ x,
    const float* __restrict__ Wl, const float* __restrict__ bl,
    const float* __restrict__ Wr, const float* __restrict__ br,
    int nrows)
{
    __shared__ __half sA[2][128][48];
    __shared__ __half sB[2][128][48];

    const float* __restrict__ W  = blockIdx.y ? Wr : Wl;
    const float* __restrict__ bv = blockIdx.y ? br : bl;
    __half* __restrict__ outH    = blockIdx.y ? g_xr_h : g_xl_h;

    const int tid  = threadIdx.x;
    const int lane = tid & 31;
    const int wid  = tid >> 5;
    const int wm   = (wid & 3) * 32;
    const int wn   = (wid >> 2) * 64;
    const int rowBase = blockIdx.x * 128;

    // Loader: thread -> one row (0..127), one 16-k group within BK=32
    const int lr = tid >> 1;
    const int lg = (tid & 1) * 16;       // k-group offset (0 or 16)

    const int qid = lane >> 2;           // 0..7
    const int rid = lane & 3;            // 0..3

    float acc[2][8][4];
#pragma unroll
    for (int mt = 0; mt < 2; mt++)
#pragma unroll
        for (int nt = 0; nt < 8; nt++)
#pragma unroll
            for (int i = 0; i < 4; i++) acc[mt][nt][i] = 0.0f;

    float4 va[4], vb[4];

    auto load_tile = [&](int kt) {
        const int gr = rowBase + lr;
        if (gr < nrows) {
            const float* ap = x + (size_t)gr * F_IN + kt * 32 + lg;
#pragma unroll
            for (int j = 0; j < 4; j++)
                va[j] = *reinterpret_cast<const float4*>(ap + 4 * j);
        } else {
#pragma unroll
            for (int j = 0; j < 4; j++)
                va[j] = make_float4(0.f, 0.f, 0.f, 0.f);
        }
        const float* bp = W + (size_t)lr * F_IN + kt * 32 + lg;
#pragma unroll
        for (int j = 0; j < 4; j++)
            vb[j] = *reinterpret_cast<const float4*>(bp + 4 * j);
    };

    auto sts_tile = [&](int b) {
        // permuted order within 16-k group: [f0f1 f8f9 f2f3 f10f11 | f4f5 f12f13 f6f7 f14f15]
        *reinterpret_cast<uint4*>(&sA[b][lr][lg])     = pack8h(va[0], va[2]);
        *reinterpret_cast<uint4*>(&sA[b][lr][lg + 8]) = pack8h(va[1], va[3]);
        *reinterpret_cast<uint4*>(&sB[b][lr][lg])     = pack8h(vb[0], vb[2]);
        *reinterpret_cast<uint4*>(&sB[b][lr][lg + 8]) = pack8h(vb[1], vb[3]);
    };

    auto compute = [&](int b) {
#pragma unroll
        for (int c = 0; c < 2; c++) {
            const int kc = c * 16 + 4 * rid;
            unsigned af[2][4];
#pragma unroll
            for (int mt = 0; mt < 2; mt++) {
                uint2 t0 = *reinterpret_cast<const uint2*>(&sA[b][wm + mt * 16 + qid][kc]);
                uint2 t1 = *reinterpret_cast<const uint2*>(&sA[b][wm + mt * 16 + qid + 8][kc]);
                af[mt][0] = t0.x;   // a0: row qid,   k 2rid..2rid+1
                af[mt][1] = t1.x;   // a1: row qid+8, k 2rid..2rid+1
                af[mt][2] = t0.y;   // a2: row qid,   k 2rid+8..2rid+9
                af[mt][3] = t1.y;   // a3: row qid+8, k 2rid+8..2rid+9
            }
            unsigned bf[8][2];
#pragma unroll
            for (int nt = 0; nt < 8; nt++) {
                uint2 t = *reinterpret_cast<const uint2*>(&sB[b][wn + nt * 8 + qid][kc]);
                bf[nt][0] = t.x;    // b0
                bf[nt][1] = t.y;    // b1
            }
#pragma unroll
            for (int mt = 0; mt < 2; mt++)
#pragma unroll
                for (int nt = 0; nt < 8; nt++) {
                    asm volatile(
                        "mma.sync.aligned.m16n8k16.row.col.f32.f16.f16.f32 "
                        "{%0,%1,%2,%3}, {%4,%5,%6,%7}, {%8,%9}, {%0,%1,%2,%3};"
                        : "+f"(acc[mt][nt][0]), "+f"(acc[mt][nt][1]),
                          "+f"(acc[mt][nt][2]), "+f"(acc[mt][nt][3])
                        : "r"(af[mt][0]), "r"(af[mt][1]),
                          "r"(af[mt][2]), "r"(af[mt][3]),
                          "r"(bf[nt][0]), "r"(bf[nt][1]));
                }
        }
    };

    load_tile(0);
    sts_tile(0);
    __syncthreads();
#pragma unroll 2
    for (int kt = 0; kt < 8; kt++) {
        if (kt < 7) load_tile(kt + 1);
        compute(kt & 1);
        if (kt < 7) sts_tile((kt + 1) & 1);
        __syncthreads();
    }

    // Epilogue: bias + convert to fp16, store
#pragma unroll
    for (int mt = 0; mt < 2; mt++) {
#pragma unroll
        for (int half_ = 0; half_ < 2; half_++) {
            const int row = rowBase + wm + mt * 16 + qid + half_ * 8;
            if (row >= nrows) continue;
            __half* dst = outH + (size_t)row * HC;
#pragma unroll
            for (int nt = 0; nt < 8; nt++) {
                const int col = wn + nt * 8 + 2 * rid;
                float2 o;
                o.x = acc[mt][nt][half_ * 2 + 0] + bv[col];
                o.y = acc[mt][nt][half_ * 2 + 1] + bv[col + 1];
                *reinterpret_cast<__half2*>(dst + col) = __float22half2_rn(o);
            }
        }
    }
}

// ---------------------------------------------------------------------------
// K2: aggregation, TWO warps per destination node (halves the serial
// gather+shfl chain per warp, doubles warp-level parallelism).
// xr[dst] loaded once per warp; src list split, walked in 32-chunks via shfl
// broadcast; partials combined through smem. Softmax shift skipped
// (shift-invariant; logits are O(10), exp safe in fp32).
// Writes final out = acc/denom + bias.
// ---------------------------------------------------------------------------
__global__ __launch_bounds__(256) void agg_kernel(
    const float* __restrict__ att,   // [128]
    const float* __restrict__ bias,  // [128]
    float* __restrict__ out,         // [N, 128]
    int n)
{
    const int gtid = blockIdx.x * blockDim.x + threadIdx.x;
    const int node = gtid >> 6;                 // 64 threads (2 warps) per node
    const int sub  = (threadIdx.x >> 5) & 1;    // 0 or 1: which half of the list
    const int lane = threadIdx.x & 31;
    const int nb   = threadIdx.x >> 6;          // node slot within block (0..3)
    const int c4   = lane * 4;                  // lanes 0-15 head0, 16-31 head1

    __shared__ float red[4][32][5];

    float acc0 = 0.f, acc1 = 0.f, acc2 = 0.f, acc3 = 0.f, denom = 0.f;
    const bool valid = node < n;

    float4 a = make_float4(0.f, 0.f, 0.f, 0.f);
    float2 xr01 = make_float2(0.f, 0.f), xr23 = make_float2(0.f, 0.f);

    if (valid) {
        a = reinterpret_cast<const float4*>(att)[lane];
        const uint2 xru = *reinterpret_cast<const uint2*>(g_xr_h + (size_t)node * HC + c4);
        xr01 = __half22float2(*reinterpret_cast<const __half2*>(&xru.x));
        xr23 = __half22float2(*reinterpret_cast<const __half2*>(&xru.y));
    }

    auto process = [&](int s) {
        const uint2 xlu = *reinterpret_cast<const uint2*>(g_xl_h + (size_t)s * HC + c4);
        const float2 l01 = __half22float2(*reinterpret_cast<const __half2*>(&xlu.x));
        const float2 l23 = __half22float2(*reinterpret_cast<const __half2*>(&xlu.y));

        float sx = l01.x + xr01.x; sx = fmaxf(sx, NEG_SLOPE * sx);
        float sy = l01.y + xr01.y; sy = fmaxf(sy, NEG_SLOPE * sy);
        float sz = l23.x + xr23.x; sz = fmaxf(sz, NEG_SLOPE * sz);
        float sw = l23.y + xr23.y; sw = fmaxf(sw, NEG_SLOPE * sw);

        float part = a.x * sx + a.y * sy + a.z * sz + a.w * sw;
#pragma unroll
        for (int off = 8; off > 0; off >>= 1)
            part += __shfl_xor_sync(0xffffffffu, part, off);

        const float p = __expf(part);
        denom += p;
        acc0 += p * l01.x;
        acc1 += p * l01.y;
        acc2 += p * l23.x;
        acc3 += p * l23.y;
    };

    if (valid) {
        // Self loop (src == dst) on warp 0 only
        if (sub == 0) process(node);

        const int b0 = g_row[node];
        const int e0 = g_row[node + 1];
        const int mid = b0 + ((e0 - b0 + 1) >> 1);
        const int beg = sub ? mid : b0;
        const int end = sub ? e0 : mid;

        for (int j0 = beg; j0 < end; j0 += 32) {
            const int myidx = j0 + lane;
            const int s_l = (myidx < end) ? g_srcs[myidx] : 0;
            const int m = min(32, end - j0);
            for (int t = 0; t < m; t++) {
                const int s = __shfl_sync(0xffffffffu, s_l, t);
                process(s);
            }
        }
    }

    if (sub == 1) {
        red[nb][lane][0] = acc0;
        red[nb][lane][1] = acc1;
        red[nb][lane][2] = acc2;
        red[nb][lane][3] = acc3;
        red[nb][lane][4] = denom;
    }
    __syncthreads();
    if (valid && sub == 0) {
        acc0 += red[nb][lane][0];
        acc1 += red[nb][lane][1];
        acc2 += red[nb][lane][2];
        acc3 += red[nb][lane][3];
        denom += red[nb][lane][4];

        const float inv = 1.0f / denom;
        const float4 b = reinterpret_cast<const float4*>(bias)[lane];
        float4 o;
        o.x = acc0 * inv + b.x;
        o.y = acc1 * inv + b.y;
        o.z = acc2 * inv + b.z;
        o.w = acc3 * inv + b.w;
        *reinterpret_cast<float4*>(out + (size_t)node * HC + c4) = o;
    }
}

// ---------------------------------------------------------------------------
extern "C" void kernel_launch(void* const* d_in, const int* in_sizes, int n_in,
                              void* d_out, int out_size)
{
    const float* x    = (const float*)d_in[0];
    const float* Wl   = (const float*)d_in[1];
    const float* bl   = (const float*)d_in[2];
    const float* Wr   = (const float*)d_in[3];
    const float* br   = (const float*)d_in[4];
    const float* att  = (const float*)d_in[5];
    const float* bias = (const float*)d_in[6];
    const int*   ei   = (const int*)d_in[7];
    float* out = (float*)d_out;

    const int n = in_sizes[0] / F_IN;     // 100000
    const int E = in_sizes[7] / 2;        // 1600000
    const int nb = (n + 1023) / 1024;     // scan blocks (98 for n=100000)

    // CSR build (counting sort by destination)
    {
        int n4 = (n + 3) / 4;
        hist_zero_kernel<<<(n4 + 255) / 256, 256>>>(n4);
        hist_kernel<<<(E + 255) / 256, 256>>>(ei, E);
        scan1_kernel<<<nb, 256>>>(n);
        scan2_kernel<<<1, 256>>>(nb, n, E);
        scan3_kernel<<<nb, 256>>>(n);
        scatter_kernel<<<(E + 255) / 256, 256>>>(ei, E);
    }

    // Projection GEMM (tensor cores, fp16 m16n8k16 -> fp16 scratch)
    {
        dim3 grid((n + 127) / 128, 2);
        gemm_fp16_kernel<<<grid, 256>>>(x, Wl, bl, Wr, br, n);
    }

    // Aggregation: two warps per node, register accumulation, fused epilogue
    {
        long long totalThreads = (long long)n * 64;
        int blocks = (int)((totalThreads + 255) / 256);
        agg_kernel<<<blocks, 256>>>(att, bias, out, n);
    }
}

// round 9
// speedup vs baseline: 1.0065x; 1.0065x over previous
#include <cuda_runtime.h>
#include <cuda_fp16.h>
#include <cstdint>

// Problem constants (fixed by the dataset)
#define MAXN      100000
#define MAXE      2000000
#define F_IN      256
#define HC        128       // H*C = 2*64
#define NEG_SLOPE 0.2f

// Projected features in fp16: xl (source path) and xr (target path), [N][128]
__device__ __half g_xl_h[(size_t)MAXN * HC];
__device__ __half g_xr_h[(size_t)MAXN * HC];

// CSR-by-destination scratch
__device__ int g_cnt[MAXN + 4];      // in-degree histogram (padded for int4)
__device__ int g_row[MAXN + 1];      // row offsets
__device__ int g_cur[MAXN];          // scatter cursors
__device__ int g_srcs[MAXE];         // src node per edge, grouped by dst
__device__ int g_blksum[256];        // per-block sums for the scan
__device__ int g_blkoff[256];        // exclusive block offsets

// ---------------------------------------------------------------------------
// CSR build: zero-hist -> histogram -> 3-pass hierarchical scan -> scatter
// ---------------------------------------------------------------------------
__global__ void hist_zero_kernel(int n4) {
    int i = blockIdx.x * blockDim.x + threadIdx.x;
    if (i < n4) reinterpret_cast<int4*>(g_cnt)[i] = make_int4(0, 0, 0, 0);
}

__global__ void hist_kernel(const int* __restrict__ ei, int E) {
    int i = blockIdx.x * blockDim.x + threadIdx.x;
    if (i < E) atomicAdd(&g_cnt[ei[E + i]], 1);
}

// Pass 1: per-block (1024 elements) reduction -> g_blksum
__global__ __launch_bounds__(256) void scan1_kernel(int n) {
    const int b = blockIdx.x, tid = threadIdx.x;
    const int i0 = b * 1024 + tid * 4;
    int s0 = 0;
    if (i0 + 3 < n) {
        int4 v = *reinterpret_cast<const int4*>(&g_cnt[i0]);
        s0 = v.x + v.y + v.z + v.w;
    } else {
        for (int j = 0; j < 4; j++) if (i0 + j < n) s0 += g_cnt[i0 + j];
    }
#pragma unroll
    for (int off = 16; off; off >>= 1)
        s0 += __shfl_xor_sync(0xffffffffu, s0, off);
    __shared__ int ws[8];
    if ((tid & 31) == 0) ws[tid >> 5] = s0;
    __syncthreads();
    if (tid == 0) {
        int t = 0;
#pragma unroll
        for (int j = 0; j < 8; j++) t += ws[j];
        g_blksum[b] = t;
    }
}

// Pass 2: scan the (<=256) block sums in one block; also set g_row[n] = E
__global__ __launch_bounds__(256) void scan2_kernel(int nb, int n, int E) {
    const int tid = threadIdx.x;
    int v = (tid < nb) ? g_blksum[tid] : 0;
    __shared__ int s[256];
    s[tid] = v;
    __syncthreads();
#pragma unroll
    for (int off = 1; off < 256; off <<= 1) {
        int t = (tid >= off) ? s[tid - off] : 0;
        __syncthreads();
        s[tid] += t;
        __syncthreads();
    }
    if (tid < nb) g_blkoff[tid] = s[tid] - v;   // exclusive
    if (tid == 0) g_row[n] = E;
}

// Pass 3: per-block exclusive scan + block offset -> g_row, g_cur
__global__ __launch_bounds__(256) void scan3_kernel(int n) {
    const int b = blockIdx.x, tid = threadIdx.x;
    const int lane = tid & 31, wid = tid >> 5;
    const int i0 = b * 1024 + tid * 4;
    int c0 = 0, c1 = 0, c2 = 0, c3 = 0;
    if (i0 + 3 < n) {
        int4 v = *reinterpret_cast<const int4*>(&g_cnt[i0]);
        c0 = v.x; c1 = v.y; c2 = v.z; c3 = v.w;
    } else {
        if (i0 + 0 < n) c0 = g_cnt[i0 + 0];
        if (i0 + 1 < n) c1 = g_cnt[i0 + 1];
        if (i0 + 2 < n) c2 = g_cnt[i0 + 2];
        if (i0 + 3 < n) c3 = g_cnt[i0 + 3];
    }
    const int tsum = c0 + c1 + c2 + c3;
    int incl = tsum;
#pragma unroll
    for (int off = 1; off < 32; off <<= 1) {
        int t = __shfl_up_sync(0xffffffffu, incl, off);
        if (lane >= off) incl += t;
    }
    const int excl = incl - tsum;
    __shared__ int ws[8];
    __shared__ int wso[8];
    if (lane == 31) ws[wid] = incl;
    __syncthreads();
    if (tid == 0) {
        int r = 0;
#pragma unroll
        for (int j = 0; j < 8; j++) { wso[j] = r; r += ws[j]; }
    }
    __syncthreads();
    int base = g_blkoff[b] + wso[wid] + excl;
    if (i0 + 0 < n) { g_row[i0 + 0] = base; g_cur[i0 + 0] = base; base += c0; }
    if (i0 + 1 < n) { g_row[i0 + 1] = base; g_cur[i0 + 1] = base; base += c1; }
    if (i0 + 2 < n) { g_row[i0 + 2] = base; g_cur[i0 + 2] = base; base += c2; }
    if (i0 + 3 < n) { g_row[i0 + 3] = base; g_cur[i0 + 3] = base; base += c3; }
}

__global__ void scatter_kernel(const int* __restrict__ ei, int E) {
    int i = blockIdx.x * blockDim.x + threadIdx.x;
    if (i >= E) return;
    int s = ei[i];
    int d = ei[E + i];
    int pos = atomicAdd(&g_cur[d], 1);
    g_srcs[pos] = s;
}

// ---------------------------------------------------------------------------
// K1: fp16 tensor-core projection GEMM (m16n8k16, fp32 accumulate).
//   blockIdx.y == 0 : xl = x @ Wl^T + bl -> g_xl_h
//   blockIdx.y == 1 : xr = x @ Wr^T + br -> g_xr_h
// 128x128 block tile, BK=32 double-buffered, 8 warps (4Mx2N),
// warp tile 32x64 = 2x8 mma tiles of m16n8k16.
// Smem k-permute per 16-k group: order [0,1,8,9, 2,3,10,11, 4,5,12,13,
// 6,7,14,15], so each thread's fragment pairs (k,k+1) and (k+8,k+9) are
// 4 consecutive halves -> single LDS.64 per fragment pair.
// Rows padded to 48 halves (96B = 24 banks -> conflict-free 16-lane phases).
// ---------------------------------------------------------------------------
__device__ __forceinline__ uint4 pack8h(float4 p, float4 q) {
    // halves order: p0 p1 q0 q1 p2 p3 q2 q3  (matches the k-permute)
    uint4 r;
    __half2 h;
    h = __float22half2_rn(make_float2(p.x, p.y)); r.x = *reinterpret_cast<unsigned*>(&h);
    h = __float22half2_rn(make_float2(q.x, q.y)); r.y = *reinterpret_cast<unsigned*>(&h);
    h = __float22half2_rn(make_float2(p.z, p.w)); r.z = *reinterpret_cast<unsigned*>(&h);
    h = __float22half2_rn(make_float2(q.z, q.w)); r.w = *reinterpret_cast<unsigned*>(&h);
    return r;
}

__global__ __launch_bounds__(256) void gemm_fp16_kernel(
    const float* __restrict__ x,
    const float* __restrict__ Wl, const float* __restrict__ bl,
    const float* __restrict__ Wr, const float* __restrict__ br,
    int nrows)
{
    __shared__ __half sA[2][128][48];
    __shared__ __half sB[2][128][48];

    const float* __restrict__ W  = blockIdx.y ? Wr : Wl;
    const float* __restrict__ bv = blockIdx.y ? br : bl;
    __half* __restrict__ outH    = blockIdx.y ? g_xr_h : g_xl_h;

    const int tid  = threadIdx.x;
    const int lane = tid & 31;
    const int wid  = tid >> 5;
    const int wm   = (wid & 3) * 32;
    const int wn   = (wid >> 2) * 64;
    const int rowBase = blockIdx.x * 128;

    // Loader: thread -> one row (0..127), one 16-k group within BK=32
    const int lr = tid >> 1;
    const int lg = (tid & 1) * 16;       // k-group offset (0 or 16)

    const int qid = lane >> 2;           // 0..7
    const int rid = lane & 3;            // 0..3

    float acc[2][8][4];
#pragma unroll
    for (int mt = 0; mt < 2; mt++)
#pragma unroll
        for (int nt = 0; nt < 8; nt++)
#pragma unroll
            for (int i = 0; i < 4; i++) acc[mt][nt][i] = 0.0f;

    float4 va[4], vb[4];

    auto load_tile = [&](int kt) {
        const int gr = rowBase + lr;
        if (gr < nrows) {
            const float* ap = x + (size_t)gr * F_IN + kt * 32 + lg;
#pragma unroll
            for (int j = 0; j < 4; j++)
                va[j] = *reinterpret_cast<const float4*>(ap + 4 * j);
        } else {
#pragma unroll
            for (int j = 0; j < 4; j++)
                va[j] = make_float4(0.f, 0.f, 0.f, 0.f);
        }
        const float* bp = W + (size_t)lr * F_IN + kt * 32 + lg;
#pragma unroll
        for (int j = 0; j < 4; j++)
            vb[j] = *reinterpret_cast<const float4*>(bp + 4 * j);
    };

    auto sts_tile = [&](int b) {
        // permuted order within 16-k group: [f0f1 f8f9 f2f3 f10f11 | f4f5 f12f13 f6f7 f14f15]
        *reinterpret_cast<uint4*>(&sA[b][lr][lg])     = pack8h(va[0], va[2]);
        *reinterpret_cast<uint4*>(&sA[b][lr][lg + 8]) = pack8h(va[1], va[3]);
        *reinterpret_cast<uint4*>(&sB[b][lr][lg])     = pack8h(vb[0], vb[2]);
        *reinterpret_cast<uint4*>(&sB[b][lr][lg + 8]) = pack8h(vb[1], vb[3]);
    };

    auto compute = [&](int b) {
#pragma unroll
        for (int c = 0; c < 2; c++) {
            const int kc = c * 16 + 4 * rid;
            unsigned af[2][4];
#pragma unroll
            for (int mt = 0; mt < 2; mt++) {
                uint2 t0 = *reinterpret_cast<const uint2*>(&sA[b][wm + mt * 16 + qid][kc]);
                uint2 t1 = *reinterpret_cast<const uint2*>(&sA[b][wm + mt * 16 + qid + 8][kc]);
                af[mt][0] = t0.x;   // a0: row qid,   k 2rid..2rid+1
                af[mt][1] = t1.x;   // a1: row qid+8, k 2rid..2rid+1
                af[mt][2] = t0.y;   // a2: row qid,   k 2rid+8..2rid+9
                af[mt][3] = t1.y;   // a3: row qid+8, k 2rid+8..2rid+9
            }
            unsigned bf[8][2];
#pragma unroll
            for (int nt = 0; nt < 8; nt++) {
                uint2 t = *reinterpret_cast<const uint2*>(&sB[b][wn + nt * 8 + qid][kc]);
                bf[nt][0] = t.x;    // b0
                bf[nt][1] = t.y;    // b1
            }
#pragma unroll
            for (int mt = 0; mt < 2; mt++)
#pragma unroll
                for (int nt = 0; nt < 8; nt++) {
                    asm volatile(
                        "mma.sync.aligned.m16n8k16.row.col.f32.f16.f16.f32 "
                        "{%0,%1,%2,%3}, {%4,%5,%6,%7}, {%8,%9}, {%0,%1,%2,%3};"
                        : "+f"(acc[mt][nt][0]), "+f"(acc[mt][nt][1]),
                          "+f"(acc[mt][nt][2]), "+f"(acc[mt][nt][3])
                        : "r"(af[mt][0]), "r"(af[mt][1]),
                          "r"(af[mt][2]), "r"(af[mt][3]),
                          "r"(bf[nt][0]), "r"(bf[nt][1]));
                }
        }
    };

    load_tile(0);
    sts_tile(0);
    __syncthreads();
#pragma unroll 2
    for (int kt = 0; kt < 8; kt++) {
        if (kt < 7) load_tile(kt + 1);
        compute(kt & 1);
        if (kt < 7) sts_tile((kt + 1) & 1);
        __syncthreads();
    }

    // Epilogue: bias + convert to fp16, store
#pragma unroll
    for (int mt = 0; mt < 2; mt++) {
#pragma unroll
        for (int half_ = 0; half_ < 2; half_++) {
            const int row = rowBase + wm + mt * 16 + qid + half_ * 8;
            if (row >= nrows) continue;
            __half* dst = outH + (size_t)row * HC;
#pragma unroll
            for (int nt = 0; nt < 8; nt++) {
                const int col = wn + nt * 8 + 2 * rid;
                float2 o;
                o.x = acc[mt][nt][half_ * 2 + 0] + bv[col];
                o.y = acc[mt][nt][half_ * 2 + 1] + bv[col + 1];
                *reinterpret_cast<__half2*>(dst + col) = __float22half2_rn(o);
            }
        }
    }
}

// ---------------------------------------------------------------------------
// K2: aggregation, TWO warps per destination node (halves the serial
// gather+shfl chain per warp, doubles warp-level parallelism).
// xr[dst] loaded once per warp; src list split, walked in 32-chunks via shfl
// broadcast; partials combined through smem. Softmax shift skipped
// (shift-invariant; logits are O(10), exp safe in fp32).
// Writes final out = acc/denom + bias.
// ---------------------------------------------------------------------------
__global__ __launch_bounds__(256) void agg_kernel(
    const float* __restrict__ att,   // [128]
    const float* __restrict__ bias,  // [128]
    float* __restrict__ out,         // [N, 128]
    int n)
{
    const int gtid = blockIdx.x * blockDim.x + threadIdx.x;
    const int node = gtid >> 6;                 // 64 threads (2 warps) per node
    const int sub  = (threadIdx.x >> 5) & 1;    // 0 or 1: which half of the list
    const int lane = threadIdx.x & 31;
    const int nb   = threadIdx.x >> 6;          // node slot within block (0..3)
    const int c4   = lane * 4;                  // lanes 0-15 head0, 16-31 head1

    __shared__ float red[4][32][5];

    float acc0 = 0.f, acc1 = 0.f, acc2 = 0.f, acc3 = 0.f, denom = 0.f;
    const bool valid = node < n;

    float4 a = make_float4(0.f, 0.f, 0.f, 0.f);
    float2 xr01 = make_float2(0.f, 0.f), xr23 = make_float2(0.f, 0.f);

    if (valid) {
        a = reinterpret_cast<const float4*>(att)[lane];
        const uint2 xru = *reinterpret_cast<const uint2*>(g_xr_h + (size_t)node * HC + c4);
        xr01 = __half22float2(*reinterpret_cast<const __half2*>(&xru.x));
        xr23 = __half22float2(*reinterpret_cast<const __half2*>(&xru.y));
    }

    auto process = [&](int s) {
        const uint2 xlu = *reinterpret_cast<const uint2*>(g_xl_h + (size_t)s * HC + c4);
        const float2 l01 = __half22float2(*reinterpret_cast<const __half2*>(&xlu.x));
        const float2 l23 = __half22float2(*reinterpret_cast<const __half2*>(&xlu.y));

        float sx = l01.x + xr01.x; sx = fmaxf(sx, NEG_SLOPE * sx);
        float sy = l01.y + xr01.y; sy = fmaxf(sy, NEG_SLOPE * sy);
        float sz = l23.x + xr23.x; sz = fmaxf(sz, NEG_SLOPE * sz);
        float sw = l23.y + xr23.y; sw = fmaxf(sw, NEG_SLOPE * sw);

        float part = a.x * sx + a.y * sy + a.z * sz + a.w * sw;
#pragma unroll
        for (int off = 8; off > 0; off >>= 1)
            part += __shfl_xor_sync(0xffffffffu, part, off);

        const float p = __expf(part);
        denom += p;
        acc0 += p * l01.x;
        acc1 += p * l01.y;
        acc2 += p * l23.x;
        acc3 += p * l23.y;
    };

    if (valid) {
        // Self loop (src == dst) on warp 0 only
        if (sub == 0) process(node);

        const int b0 = g_row[node];
        const int e0 = g_row[node + 1];
        const int mid = b0 + ((e0 - b0 + 1) >> 1);
        const int beg = sub ? mid : b0;
        const int end = sub ? e0 : mid;

        for (int j0 = beg; j0 < end; j0 += 32) {
            const int myidx = j0 + lane;
            const int s_l = (myidx < end) ? g_srcs[myidx] : 0;
            const int m = min(32, end - j0);
            for (int t = 0; t < m; t++) {
                const int s = __shfl_sync(0xffffffffu, s_l, t);
                process(s);
            }
        }
    }

    if (sub == 1) {
        red[nb][lane][0] = acc0;
        red[nb][lane][1] = acc1;
        red[nb][lane][2] = acc2;
        red[nb][lane][3] = acc3;
        red[nb][lane][4] = denom;
    }
    __syncthreads();
    if (valid && sub == 0) {
        acc0 += red[nb][lane][0];
        acc1 += red[nb][lane][1];
        acc2 += red[nb][lane][2];
        acc3 += red[nb][lane][3];
        denom += red[nb][lane][4];

        const float inv = 1.0f / denom;
        const float4 b = reinterpret_cast<const float4*>(bias)[lane];
        float4 o;
        o.x = acc0 * inv + b.x;
        o.y = acc1 * inv + b.y;
        o.z = acc2 * inv + b.z;
        o.w = acc3 * inv + b.w;
        *reinterpret_cast<float4*>(out + (size_t)node * HC + c4) = o;
    }
}

// ---------------------------------------------------------------------------
extern "C" void kernel_launch(void* const* d_in, const int* in_sizes, int n_in,
                              void* d_out, int out_size)
{
    const float* x    = (const float*)d_in[0];
    const float* Wl   = (const float*)d_in[1];
    const float* bl   = (const float*)d_in[2];
    const float* Wr   = (const float*)d_in[3];
    const float* br   = (const float*)d_in[4];
    const float* att  = (const float*)d_in[5];
    const float* bias = (const float*)d_in[6];
    const int*   ei   = (const int*)d_in[7];
    float* out = (float*)d_out;

    const int n = in_sizes[0] / F_IN;     // 100000
    const int E = in_sizes[7] / 2;        // 1600000
    const int nb = (n + 1023) / 1024;     // scan blocks (98 for n=100000)

    // CSR build (counting sort by destination)
    {
        int n4 = (n + 3) / 4;
        hist_zero_kernel<<<(n4 + 255) / 256, 256>>>(n4);
        hist_kernel<<<(E + 255) / 256, 256>>>(ei, E);
        scan1_kernel<<<nb, 256>>>(n);
        scan2_kernel<<<1, 256>>>(nb, n, E);
        scan3_kernel<<<nb, 256>>>(n);
        scatter_kernel<<<(E + 255) / 256, 256>>>(ei, E);
    }

    // Projection GEMM (tensor cores, fp16 m16n8k16 -> fp16 scratch)
    {
        dim3 grid((n + 127) / 128, 2);
        gemm_fp16_kernel<<<grid, 256>>>(x, Wl, bl, Wr, br, n);
    }

    // Aggregation: two warps per node, register accumulation, fused epilogue
    {
        long long totalThreads = (long long)n * 64;
        int blocks = (int)((totalThreads + 255) / 256);
        agg_kernel<<<blocks, 256>>>(att, bias, out, n);
    }
}